// round 6
// baseline (speedup 1.0000x reference)
#include <cuda_runtime.h>
#include <cstddef>
#include <cstdint>

// Problem constants
#define PB 4
#define PN 16384
#define PM 16384
#define PK 16
#define PC 64
#define PO 64
#define PG 8

typedef unsigned long long ull;

// ---- f32x2 packed helpers (sm_103a FFMA2 path) ----
__device__ __forceinline__ void ffma2(ull& d, ull a, ull b, ull c) {
    asm("fma.rn.f32x2 %0, %1, %2, %3;" : "=l"(d) : "l"(a), "l"(b), "l"(c));
}
__device__ __forceinline__ void fmul2(ull& d, ull a, ull b) {
    asm("mul.rn.f32x2 %0, %1, %2;" : "=l"(d) : "l"(a), "l"(b));
}
__device__ __forceinline__ void fadd2(ull& d, ull a, ull b) {
    asm("add.rn.f32x2 %0, %1, %2;" : "=l"(d) : "l"(a), "l"(b));
}
__device__ __forceinline__ ull pack2(float lo, float hi) {
    ull r; asm("mov.b64 %0, {%1, %2};" : "=l"(r) : "f"(lo), "f"(hi)); return r;
}
__device__ __forceinline__ float2 unpack2(ull v) {
    float2 f; asm("mov.b64 {%0, %1}, %2;" : "=f"(f.x), "=f"(f.y) : "l"(v)); return f;
}
__device__ __forceinline__ ull lds64(uint32_t a) {
    ull r; asm volatile("ld.shared.b64 %0, [%1];" : "=l"(r) : "r"(a)); return r;
}
__device__ __forceinline__ float lds32(uint32_t a) {
    float r; asm volatile("ld.shared.b32 %0, [%1];" : "=f"(r) : "r"(a)); return r;
}
__device__ __forceinline__ void lds128(ull& x, ull& y, uint32_t a) {
    asm volatile("ld.shared.v2.b64 {%0,%1}, [%2];" : "=l"(x), "=l"(y) : "r"(a));
}
__device__ __forceinline__ void sts128(uint32_t a, ull x, ull y) {
    asm volatile("st.shared.v2.b64 [%0], {%1,%2};" :: "r"(a), "l"(x), "l"(y) : "memory");
}
__device__ __forceinline__ void ldg128(ull& x, ull& y, const void* p) {
    asm volatile("ld.global.nc.v2.b64 {%0,%1}, [%2];" : "=l"(x), "=l"(y) : "l"(p));
}
__device__ __forceinline__ void stg128(void* p, ull x, ull y) {
    asm volatile("st.global.v2.b64 [%0], {%1,%2};" :: "l"(p), "l"(x), "l"(y) : "memory");
}

static __device__ float g_xv[PB * PN * PO];   // x_v [B,N,64]
static __device__ float g_a [PB * PN * PG];   // per-point logit precursor [B,N,8]
static __device__ float g_c [PB * PM * PG];   // per-center logit precursor [B,M,8]
static __device__ float g_wka[PC * PG];
static __device__ float g_wqa[PC * PG];
static __device__ float g_wca[PO * PG];
static __device__ float g_c0[PG];
static __device__ float g_a0[PG];
static __device__ float g_pw1f[3 * PO];       // pe_w1 col-scaled by pe_s
static __device__ float g_cw1f[3 * PO];       // cpe_w1 col-scaled by cpe_s
static __device__ float g_we2i[64];           // we_w2 interleaved pairs {w[gp][q], w[gp][q+4]}
static __device__ float g_web2i[8];           // we_b2 interleaved {b[q], b[q+4]}
static __device__ float g_pw2p[4096];         // pe_w2 paired: slot(j,q,rp) -> {w[j][8q+2rp], w[j][8q+2rp+32], w[j][8q+2rp+1], w[j][8q+2rp+33]}

// ---------------------------------------------------------------------------
// Kernel 0: fold small weight combos
// ---------------------------------------------------------------------------
__global__ void fold_kernel(const float* __restrict__ Wq, const float* __restrict__ bq,
                            const float* __restrict__ Wk, const float* __restrict__ bk,
                            const float* __restrict__ cpe_w1, const float* __restrict__ cpe_s,
                            const float* __restrict__ cpe_w2, const float* __restrict__ cpe_b2,
                            const float* __restrict__ pe_w1, const float* __restrict__ pe_s,
                            const float* __restrict__ pe_w2,
                            const float* __restrict__ we_w1, const float* __restrict__ we_s,
                            const float* __restrict__ we_b,
                            const float* __restrict__ we_w2, const float* __restrict__ we_b2) {
    int tid = threadIdx.x;             // 512 threads
    int c = tid >> 3, g = tid & 7;
    float s = we_s[g];
    float aK = 0.f, aQ = 0.f, aC = 0.f;
    #pragma unroll 8
    for (int o = 0; o < 64; o++) {
        float w1 = we_w1[o * 8 + g];
        aK = fmaf(Wk[c * 64 + o],     w1, aK);
        aQ = fmaf(Wq[c * 64 + o],     w1, aQ);
        aC = fmaf(cpe_w2[c * 64 + o], w1, aC);
    }
    g_wka[c * 8 + g] = aK * s;
    g_wqa[c * 8 + g] = aQ * s;
    g_wca[c * 8 + g] = aC * s;

    if (tid < 8) {
        float a0 = 0.f, c0 = 0.f;
        for (int o = 0; o < 64; o++) {
            float w1 = we_w1[o * 8 + tid];
            a0 = fmaf(bk[o], w1, a0);
            c0 = fmaf(bq[o] - cpe_b2[o], w1, c0);
        }
        g_a0[tid] = a0 * we_s[tid];
        g_c0[tid] = c0 * we_s[tid] - we_b[tid];
    }
    if (tid < 192) {
        int j = tid % 64;
        g_pw1f[tid] = pe_w1[tid]  * pe_s[j];
        g_cw1f[tid] = cpe_w1[tid] * cpe_s[j];
    }
    // interleaved we_w2 pairs: I[gp][2q+h] = we_w2[gp*8 + q + 4h]
    if (tid < 64) {
        int gp = tid >> 3, q = (tid & 7) >> 1, h = tid & 1;
        g_we2i[tid] = we_w2[gp * 8 + q + 4 * h];
    }
    if (tid < 8) {
        int q = tid >> 1, h = tid & 1;
        g_web2i[tid] = we_b2[q + 4 * h];
    }
    // paired pe_w2: 1024 slots of 4 floats; slot s: j=s>>4, q=(s>>2)&3, rp=s&3
    #pragma unroll
    for (int w = 0; w < 2; w++) {
        int sl = tid * 2 + w;
        int j = sl >> 4, q = (sl >> 2) & 3, rp = sl & 3;
        int o0 = 8 * q + 2 * rp;
        float4 v;
        v.x = pe_w2[j * 64 + o0];
        v.y = pe_w2[j * 64 + o0 + 32];
        v.z = pe_w2[j * 64 + o0 + 1];
        v.w = pe_w2[j * 64 + o0 + 33];
        *(float4*)(g_pw2p + sl * 4) = v;
    }
}

// ---------------------------------------------------------------------------
// Kernel 1: per-point precompute with packed f32x2 accumulators.
// ---------------------------------------------------------------------------
__global__ void __launch_bounds__(256, 2)
point_kernel(const float* __restrict__ fea,
             const float* __restrict__ Wv,
             const float* __restrict__ bv) {
    __shared__ float sWv[64 * 64];
    __shared__ float sWka[64 * 8];
    __shared__ float sbv[64];
    __shared__ float sa0[8];
    int tid = threadIdx.x;
    for (int i = tid; i < 4096; i += 256) sWv[i] = Wv[i];
    for (int i = tid; i < 512; i += 256)  sWka[i] = g_wka[i];
    if (tid < 64) sbv[tid] = bv[tid];
    if (tid < 8)  sa0[tid] = g_a0[tid];
    __syncthreads();

    uint32_t aWv = (uint32_t)__cvta_generic_to_shared(sWv);
    uint32_t aKa = (uint32_t)__cvta_generic_to_shared(sWka);
    uint32_t aBv = (uint32_t)__cvta_generic_to_shared(sbv);
    uint32_t aA0 = (uint32_t)__cvta_generic_to_shared(sa0);

    int gp = blockIdx.x * 256 + tid;
    int b = gp >> 14;
    int n = gp & (PN - 1);
    const float* fp = fea + (size_t)b * PC * PN + n;

    ull acc2[32];
    ull ag2[4];
    #pragma unroll
    for (int i = 0; i < 32; i++) acc2[i] = lds64(aBv + i * 8);
    #pragma unroll
    for (int i = 0; i < 4; i++)  ag2[i]  = lds64(aA0 + i * 8);

    #pragma unroll 4
    for (int c = 0; c < 64; c++) {
        float f = fp[(size_t)c * PN];
        ull ff = pack2(f, f);
        uint32_t rowa = aWv + c * 256;
        #pragma unroll
        for (int p = 0; p < 16; p++) {
            ull w0, w1;
            lds128(w0, w1, rowa + p * 16);
            ffma2(acc2[p * 2 + 0], ff, w0, acc2[p * 2 + 0]);
            ffma2(acc2[p * 2 + 1], ff, w1, acc2[p * 2 + 1]);
        }
        ull k0, k1, k2, k3;
        lds128(k0, k1, aKa + c * 32);
        lds128(k2, k3, aKa + c * 32 + 16);
        ffma2(ag2[0], ff, k0, ag2[0]);
        ffma2(ag2[1], ff, k1, ag2[1]);
        ffma2(ag2[2], ff, k2, ag2[2]);
        ffma2(ag2[3], ff, k3, ag2[3]);
    }

    float* ov = g_xv + (size_t)gp * 64;
    #pragma unroll
    for (int p = 0; p < 16; p++)
        stg128(ov + p * 4, acc2[p * 2], acc2[p * 2 + 1]);
    float* av = g_a + (size_t)gp * 8;
    stg128(av,     ag2[0], ag2[1]);
    stg128(av + 4, ag2[2], ag2[3]);
}

// ---------------------------------------------------------------------------
// Kernel 2: per-center precompute
// ---------------------------------------------------------------------------
__global__ void center_kernel(const float* __restrict__ center_pos,
                              const float* __restrict__ center_fea,
                              const float* __restrict__ cpe_b) {
    __shared__ float sWqa[512];
    __shared__ float sWca[512];
    __shared__ float sw1[192];
    __shared__ float sb1[64];
    int tid = threadIdx.x;
    for (int i = tid; i < 512; i += 256) { sWqa[i] = g_wqa[i]; sWca[i] = g_wca[i]; }
    if (tid < 192) sw1[tid] = g_cw1f[tid];
    if (tid < 64)  sb1[tid] = cpe_b[tid];
    __syncthreads();

    int gid = blockIdx.x * 256 + tid;
    float px = center_pos[(size_t)gid * 3 + 0];
    float py = center_pos[(size_t)gid * 3 + 1];
    float pz = center_pos[(size_t)gid * 3 + 2];

    float acc[8];
    #pragma unroll
    for (int g = 0; g < 8; g++) acc[g] = __ldg(g_c0 + g);

    int b = gid >> 14;
    int m = gid & (PM - 1);
    const float* cf = center_fea + (size_t)b * PC * PM + m;
    #pragma unroll 4
    for (int i = 0; i < 64; i++) {
        float h = fmaxf(fmaf(px, sw1[i], fmaf(py, sw1[64 + i], fmaf(pz, sw1[128 + i], sb1[i]))), 0.f);
        float f = cf[(size_t)i * PM];
        const float4* qa = (const float4*)(sWqa + i * 8);
        const float4* ca = (const float4*)(sWca + i * 8);
        float4 q0 = qa[0], q1 = qa[1], c0 = ca[0], c1 = ca[1];
        acc[0] += f * q0.x - h * c0.x;  acc[1] += f * q0.y - h * c0.y;
        acc[2] += f * q0.z - h * c0.z;  acc[3] += f * q0.w - h * c0.w;
        acc[4] += f * q1.x - h * c1.x;  acc[5] += f * q1.y - h * c1.y;
        acc[6] += f * q1.z - h * c1.z;  acc[7] += f * q1.w - h * c1.w;
    }
    float4* cv = (float4*)(g_c + (size_t)gid * 8);
    cv[0] = make_float4(acc[0], acc[1], acc[2], acc[3]);
    cv[1] = make_float4(acc[4], acc[5], acc[6], acc[7]);
}

// ---------------------------------------------------------------------------
// Kernel 3: main attention. 128 thr/block = 8 centers x 16 threads.
// H accumulators pair groups {g, g+4}; weights staged as natural interleaved
// pairs {e_g, e_g+4} (no duplication -> 2 LDS.128/k). Softmax: no max-sub,
// normalization deferred to a single post-loop packed scale.
// ---------------------------------------------------------------------------
// smem float layout:
//   0     s_we2i  [64]
//   64    s_web2i [8]
//   72    s_ikd   [8*16 float4] = 512   ({dx,dy,dz,ik_bits})
//   584   s_we    [8*16*8] = 1024       (interleaved raw-e pairs; s_out overlay)
//   1608  s_H     [8 ci * 4 q * 132] = 4224  (pair rows {H[q][j],H[q+4][j]}, pad 4)
#define SM_WE2I  0
#define SM_WEB2I 64
#define SM_IKD   72
#define SM_WE    584
#define SM_HB    1608
#define SM_TOT   (1608 + 8 * 4 * 132)

__global__ void __launch_bounds__(128, 5)
attn_kernel(const float* __restrict__ center_pos,
            const float* __restrict__ pos,
            const int* __restrict__ idx,
            const float* __restrict__ pe_b,
            const float* __restrict__ pe_b2,
            float* __restrict__ out) {
    extern __shared__ float sm[];
    float*  s_we2i = sm + SM_WE2I;
    float4* s_ikd  = (float4*)(sm + SM_IKD);
    float*  s_H    = sm + SM_HB;

    const int tid = threadIdx.x;
    if (tid < 64) s_we2i[tid] = g_we2i[tid];
    if (tid >= 64 && tid < 72) sm[SM_WEB2I + tid - 64] = g_web2i[tid - 64];
    __syncthreads();

    const unsigned FULL = 0xffffffffu;
    const int ci = tid >> 4;           // center within block (0..7)
    const int t  = tid & 15;           // lane within center
    const int g  = t >> 1;             // group for onv
    const int gidBase = blockIdx.x * 8;
    const int gid = gidBase + ci;
    const int b = gid >> 14;

    const uint32_t aBase = (uint32_t)__cvta_generic_to_shared(sm);
    const uint32_t aWE   = aBase + SM_WE * 4 + ci * 512;     // this center's e-pairs

    // --- prologue: my edge (k = t) ---
    int myik;
    {
        int ik = idx[(size_t)gid * 16 + t];
        myik = b * PN + ik;
        const float* pp = pos + (size_t)myik * 3;
        float cx = center_pos[(size_t)gid * 3 + 0];
        float cy = center_pos[(size_t)gid * 3 + 1];
        float cz = center_pos[(size_t)gid * 3 + 2];
        s_ikd[ci * 16 + t] = make_float4(pp[0] - cx, pp[1] - cy, pp[2] - cz,
                                         __int_as_float(myik));
    }

    // --- logits (packed pairs over {q, q+4}) + raw exp + sum ---
    ull invP[4];
    {
        const float4* cpv = (const float4*)(g_c + (size_t)gid * 8);
        float4 cA = cpv[0], cB = cpv[1];
        const float4* ap = (const float4*)(g_a + (size_t)myik * 8);
        float4 a0 = ap[0], a1 = ap[1];
        float h1[8];
        h1[0] = fmaxf(a0.x - cA.x, 0.f); h1[1] = fmaxf(a0.y - cA.y, 0.f);
        h1[2] = fmaxf(a0.z - cA.z, 0.f); h1[3] = fmaxf(a0.w - cA.w, 0.f);
        h1[4] = fmaxf(a1.x - cB.x, 0.f); h1[5] = fmaxf(a1.y - cB.y, 0.f);
        h1[6] = fmaxf(a1.z - cB.z, 0.f); h1[7] = fmaxf(a1.w - cB.w, 0.f);

        ull lgP[4];
        lds128(lgP[0], lgP[1], aBase + SM_WEB2I * 4);
        lds128(lgP[2], lgP[3], aBase + SM_WEB2I * 4 + 16);
        #pragma unroll
        for (int gp = 0; gp < 8; gp++) {
            ull w01, w23, w45, w67;
            lds128(w01, w23, aBase + SM_WE2I * 4 + gp * 32);
            lds128(w45, w67, aBase + SM_WE2I * 4 + gp * 32 + 16);
            ull hd = pack2(h1[gp], h1[gp]);
            ffma2(lgP[0], hd, w01, lgP[0]);
            ffma2(lgP[1], hd, w23, lgP[1]);
            ffma2(lgP[2], hd, w45, lgP[2]);
            ffma2(lgP[3], hd, w67, lgP[3]);
        }
        // raw exp (no max-sub: logits are O(0.1))
        ull eP[4], sumP[4];
        #pragma unroll
        for (int q = 0; q < 4; q++) {
            float2 lv = unpack2(lgP[q]);
            eP[q] = pack2(__expf(lv.x), __expf(lv.y));
            sumP[q] = eP[q];
        }
        // store raw-e pairs for this edge
        sts128(aWE + t * 32,      eP[0], eP[1]);
        sts128(aWE + t * 32 + 16, eP[2], eP[3]);
        // packed sum butterfly over 16 lanes
        #pragma unroll
        for (int s = 1; s < 16; s <<= 1) {
            #pragma unroll
            for (int q = 0; q < 4; q++) {
                ull o = __shfl_xor_sync(FULL, sumP[q], s, 16);
                fadd2(sumP[q], sumP[q], o);
            }
        }
        #pragma unroll
        for (int q = 0; q < 4; q++) {
            float2 sv = unpack2(sumP[q]);
            invP[q] = pack2(__fdividef(1.f, sv.x), __fdividef(1.f, sv.y));
        }
    }
    __syncwarp();

    // --- per-thread pe_w1 slice (folded with pe_s) + bias ---
    float wxa[4], wxb[4], wxc[4], bb[4];
    #pragma unroll
    for (int jj = 0; jj < 4; jj++) {
        wxa[jj] = __ldg(g_pw1f + 0 * 64 + t * 4 + jj);
        wxb[jj] = __ldg(g_pw1f + 1 * 64 + t * 4 + jj);
        wxc[jj] = __ldg(g_pw1f + 2 * 64 + t * 4 + jj);
        bb[jj]  = __ldg(pe_b + t * 4 + jj);
    }

    // --- edge loop ---
    // Hc2[jl*4+q] = {H[q][4t+jl], H[q+4][4t+jl]}  (unnormalized)
    ull Hc2[16];
    ull onv2[2] = {0ull, 0ull};
    #pragma unroll
    for (int i = 0; i < 16; i++) Hc2[i] = 0ull;

    const uint32_t wtOff = aWE + ((g & 3) * 2 + (g >> 2)) * 4;   // scalar e_g per edge
    #pragma unroll
    for (int k = 0; k < 16; k++) {
        float4 d = *(float4*)((char*)sm + (SM_IKD * 4 + ci * 256 + k * 16));
        int ikk = __float_as_int(d.w);
        ull wp0, wp1, wp2, wp3;
        lds128(wp0, wp1, aWE + k * 32);
        lds128(wp2, wp3, aWE + k * 32 + 16);
        float wt = lds32(wtOff + k * 32);
        ull v0, v1;
        ldg128(v0, v1, g_xv + (size_t)ikk * 64 + t * 4);

        float h0 = fmaxf(fmaf(d.x, wxa[0], fmaf(d.y, wxb[0], fmaf(d.z, wxc[0], bb[0]))), 0.f);
        float h1 = fmaxf(fmaf(d.x, wxa[1], fmaf(d.y, wxb[1], fmaf(d.z, wxc[1], bb[1]))), 0.f);
        float h2 = fmaxf(fmaf(d.x, wxa[2], fmaf(d.y, wxb[2], fmaf(d.z, wxc[2], bb[2]))), 0.f);
        float h3 = fmaxf(fmaf(d.x, wxa[3], fmaf(d.y, wxb[3], fmaf(d.z, wxc[3], bb[3]))), 0.f);
        ull hd0 = pack2(h0, h0), hd1 = pack2(h1, h1);
        ull hd2 = pack2(h2, h2), hd3 = pack2(h3, h3);

        ffma2(Hc2[0],  wp0, hd0, Hc2[0]);  ffma2(Hc2[1],  wp1, hd0, Hc2[1]);
        ffma2(Hc2[2],  wp2, hd0, Hc2[2]);  ffma2(Hc2[3],  wp3, hd0, Hc2[3]);
        ffma2(Hc2[4],  wp0, hd1, Hc2[4]);  ffma2(Hc2[5],  wp1, hd1, Hc2[5]);
        ffma2(Hc2[6],  wp2, hd1, Hc2[6]);  ffma2(Hc2[7],  wp3, hd1, Hc2[7]);
        ffma2(Hc2[8],  wp0, hd2, Hc2[8]);  ffma2(Hc2[9],  wp1, hd2, Hc2[9]);
        ffma2(Hc2[10], wp2, hd2, Hc2[10]); ffma2(Hc2[11], wp3, hd2, Hc2[11]);
        ffma2(Hc2[12], wp0, hd3, Hc2[12]); ffma2(Hc2[13], wp1, hd3, Hc2[13]);
        ffma2(Hc2[14], wp2, hd3, Hc2[14]); ffma2(Hc2[15], wp3, hd3, Hc2[15]);

        ull wtp = pack2(wt, wt);
        ffma2(onv2[0], wtp, v0, onv2[0]);
        ffma2(onv2[1], wtp, v1, onv2[1]);
    }

    // --- normalize: Hc2 *= invP[q];  onv2 *= inv_g ---
    #pragma unroll
    for (int jl = 0; jl < 4; jl++)
        #pragma unroll
        for (int q = 0; q < 4; q++)
            fmul2(Hc2[jl * 4 + q], Hc2[jl * 4 + q], invP[q]);
    {
        ull ip = (g & 3) == 0 ? invP[0] : (g & 3) == 1 ? invP[1] : (g & 3) == 2 ? invP[2] : invP[3];
        float2 iv = unpack2(ip);
        float invg = (g >> 2) ? iv.y : iv.x;
        ull ig = pack2(invg, invg);
        fmul2(onv2[0], onv2[0], ig);
        fmul2(onv2[1], onv2[1], ig);
    }

    // --- store H pair-rows to smem (warp-local) ---
    {
        uint32_t aH = aBase + SM_HB * 4 + ci * 4 * 528 + t * 32;
        #pragma unroll
        for (int q = 0; q < 4; q++) {
            sts128(aH + q * 528,      Hc2[0 * 4 + q], Hc2[1 * 4 + q]);
            sts128(aH + q * 528 + 16, Hc2[2 * 4 + q], Hc2[3 * 4 + q]);
        }
    }
    __syncthreads();   // all warps past s_we reads -> safe to overlay s_out

    // --- phase 1: onv to staging (o = 4t..4t+3) ---
    float* s_out = sm + SM_WE;   // 64 x 9 overlay
    {
        float2 a0 = unpack2(onv2[0]), a1 = unpack2(onv2[1]);
        s_out[(t * 4 + 0) * 9 + ci] = a0.x;
        s_out[(t * 4 + 1) * 9 + ci] = a0.y;
        s_out[(t * 4 + 2) * 9 + ci] = a1.x;
        s_out[(t * 4 + 3) * 9 + ci] = a1.y;
    }

    // --- pr contraction: thread (q=t&3, rp=t>>2) -> outputs {oa0,oa1} and +32 ---
    const int q  = t & 3;
    const int rp = t >> 2;
    const int oa0 = 8 * q + 2 * rp;
    ull prP0 = pack2(__ldg(pe_b2 + oa0),     __ldg(pe_b2 + oa0 + 32));
    ull prP1 = pack2(__ldg(pe_b2 + oa0 + 1), __ldg(pe_b2 + oa0 + 33));
    {
        uint32_t aHr = aBase + SM_HB * 4 + (ci * 4 + q) * 528;
        const float* wp = g_pw2p + (q * 4 + rp) * 4;
        #pragma unroll 8
        for (int j = 0; j < 64; j += 2) {
            ull Hj0, Hj1;
            lds128(Hj0, Hj1, aHr + j * 8);
            ull p0, p1;
            ldg128(p0, p1, wp + j * 64);
            ffma2(prP0, Hj0, p0, prP0);
            ffma2(prP1, Hj0, p1, prP1);
            ldg128(p0, p1, wp + (j + 1) * 64);
            ffma2(prP0, Hj1, p0, prP0);
            ffma2(prP1, Hj1, p1, prP1);
        }
    }
    __syncthreads();   // onv staging complete everywhere

    // --- phase 2: add pr at its o-mapping ---
    {
        float2 P0 = unpack2(prP0), P1 = unpack2(prP1);
        s_out[(oa0)      * 9 + ci] += P0.x;
        s_out[(oa0 + 1)  * 9 + ci] += P1.x;
        s_out[(oa0 + 32) * 9 + ci] += P0.y;
        s_out[(oa0 + 33) * 9 + ci] += P1.y;
    }
    __syncthreads();

    const int m0 = gidBase & (PM - 1);
    float* ob = out + (size_t)(gidBase >> 14) * PO * PM + m0;
    #pragma unroll
    for (int qq = 0; qq < 4; qq++) {
        int lin = qq * 128 + tid;
        int o = lin >> 3;
        int ml = lin & 7;
        ob[(size_t)o * PM + ml] = s_out[o * 9 + ml];
    }
}

// ---------------------------------------------------------------------------
extern "C" void kernel_launch(void* const* d_in, const int* in_sizes, int n_in,
                              void* d_out, int out_size) {
    (void)in_sizes; (void)n_in; (void)out_size;
    const float* center_pos = (const float*)d_in[0];
    const float* center_fea = (const float*)d_in[1];
    const float* pos        = (const float*)d_in[2];
    const float* fea        = (const float*)d_in[3];
    const int*   idx        = (const int*)d_in[4];
    const float* Wq  = (const float*)d_in[5];
    const float* bq  = (const float*)d_in[6];
    const float* Wk  = (const float*)d_in[7];
    const float* bk  = (const float*)d_in[8];
    const float* Wv  = (const float*)d_in[9];
    const float* bv  = (const float*)d_in[10];
    const float* cpe_w1 = (const float*)d_in[11];
    const float* cpe_s  = (const float*)d_in[12];
    const float* cpe_b  = (const float*)d_in[13];
    const float* cpe_w2 = (const float*)d_in[14];
    const float* cpe_b2 = (const float*)d_in[15];
    const float* pe_w1  = (const float*)d_in[16];
    const float* pe_s   = (const float*)d_in[17];
    const float* pe_b   = (const float*)d_in[18];
    const float* pe_w2  = (const float*)d_in[19];
    const float* pe_b2  = (const float*)d_in[20];
    const float* we_w1  = (const float*)d_in[21];
    const float* we_s   = (const float*)d_in[22];
    const float* we_b   = (const float*)d_in[23];
    const float* we_w2  = (const float*)d_in[24];
    const float* we_b2  = (const float*)d_in[25];
    float* out = (float*)d_out;

    fold_kernel<<<1, 512>>>(Wq, bq, Wk, bk, cpe_w1, cpe_s, cpe_w2, cpe_b2,
                            pe_w1, pe_s, pe_w2, we_w1, we_s, we_b, we_w2, we_b2);
    point_kernel<<<(PB * PN) / 256, 256>>>(fea, Wv, bv);
    center_kernel<<<(PB * PM) / 256, 256>>>(center_pos, center_fea, cpe_b);

    const int smem = SM_TOT * 4;   // ~23.3 KB
    cudaFuncSetAttribute(attn_kernel, cudaFuncAttributeMaxDynamicSharedMemorySize, smem);
    attn_kernel<<<(PB * PM) / 8, 128, smem>>>(center_pos, pos, idx,
                                              pe_b, pe_b2, out);
}